// round 1
// baseline (speedup 1.0000x reference)
#include <cuda_runtime.h>
#include <math.h>

#define B_  8
#define LP_ 1000
#define NC_ 64
#define D_  128
#define E_  320
#define NTILE_ 40
#define ITILE_ 25

// ---------------- scratch (device globals; no allocation allowed) ----------
__device__ float g_pe [B_*LP_*D_];   // emb output; reused as attn@V output
__device__ float g_Q  [B_*LP_*D_];
__device__ float g_K  [B_*LP_*D_];
__device__ float g_V  [B_*LP_*D_];
__device__ float g_pf [B_*LP_*D_];   // protein_feats
__device__ float g_P  [B_*LP_*D_];
__device__ float g_C  [B_*NC_*D_];
__device__ float g_S  [B_*LP_*LP_];  // attention scores / probs (32 MB)
__device__ float g_A  [B_*LP_*NC_];  // sigmoid joint attention (unnormalized)
__device__ float g_Asum[B_];
__device__ float g_part[B_*NTILE_*D_];
__device__ float g_cp [B_*D_];
__device__ float g_h1 [B_*1024];
__device__ float g_h2 [B_*1024];
__device__ float g_h3 [B_*256];

// ---------------- generic tiled fp32 GEMM ----------------------------------
// C[b] = alpha * act(A[b]) @ op(B[b]) + bias
// 64x64 tile, 256 threads, 4x4 micro-tile, K-tile 16.
template<bool TRANS_B, bool RELU_A>
__global__ void gemm_kernel(const float* __restrict__ A,
                            const float* __restrict__ Bm,
                            const float* __restrict__ bias,
                            float* __restrict__ C,
                            int M, int N, int K,
                            long long sA, long long sB, long long sC,
                            float alpha)
{
    __shared__ float As[16][68];
    __shared__ float Bs[16][68];
    int bz = blockIdx.z;
    A  += (long long)bz * sA;
    Bm += (long long)bz * sB;
    C  += (long long)bz * sC;
    int m0 = blockIdx.y * 64, n0 = blockIdx.x * 64;
    int t  = threadIdx.x;
    int tx = t & 15, ty = t >> 4;

    float acc[4][4] = {};

    for (int k0 = 0; k0 < K; k0 += 16) {
        // A tile -> As[k][m]
        #pragma unroll
        for (int e = 0; e < 4; e++) {
            int idx = t + e * 256;
            int kk = idx & 15, mm = idx >> 4;
            int gm = m0 + mm, gk = k0 + kk;
            float v = 0.f;
            if (gm < M && gk < K) v = A[(long long)gm * K + gk];
            if (RELU_A) v = fmaxf(v, 0.f);
            As[kk][mm] = v;
        }
        // B tile -> Bs[k][n]
        #pragma unroll
        for (int e = 0; e < 4; e++) {
            int idx = t + e * 256;
            if (TRANS_B) {
                int kk = idx & 15, nn = idx >> 4;
                int gn = n0 + nn, gk = k0 + kk;
                float v = 0.f;
                if (gn < N && gk < K) v = Bm[(long long)gn * K + gk];
                Bs[kk][nn] = v;
            } else {
                int nn = idx & 63, kk = idx >> 6;
                int gn = n0 + nn, gk = k0 + kk;
                float v = 0.f;
                if (gk < K && gn < N) v = Bm[(long long)gk * N + gn];
                Bs[kk][nn] = v;
            }
        }
        __syncthreads();
        #pragma unroll
        for (int kk = 0; kk < 16; kk++) {
            float a[4], b[4];
            #pragma unroll
            for (int i = 0; i < 4; i++) a[i] = As[kk][ty * 4 + i];
            #pragma unroll
            for (int j = 0; j < 4; j++) b[j] = Bs[kk][tx * 4 + j];
            #pragma unroll
            for (int i = 0; i < 4; i++)
                #pragma unroll
                for (int j = 0; j < 4; j++)
                    acc[i][j] = fmaf(a[i], b[j], acc[i][j]);
        }
        __syncthreads();
    }

    #pragma unroll
    for (int i = 0; i < 4; i++) {
        int gm = m0 + ty * 4 + i;
        if (gm >= M) continue;
        #pragma unroll
        for (int j = 0; j < 4; j++) {
            int gn = n0 + tx * 4 + j;
            if (gn >= N) continue;
            float v = acc[i][j] * alpha;
            if (bias) v += bias[gn];
            C[(long long)gm * N + gn] = v;
        }
    }
}

// ---------------- row softmax (register-resident, LP=1000) -----------------
__global__ void softmax_kernel(float* __restrict__ S)
{
    long long row = blockIdx.x;
    float* p = S + row * LP_;
    int t = threadIdx.x;  // 256
    __shared__ float red[256];

    float v[4];
    float mx = -1e30f;
    #pragma unroll
    for (int e = 0; e < 4; e++) {
        int i = t + e * 256;
        v[e] = (i < LP_) ? p[i] : -1e30f;
        mx = fmaxf(mx, v[e]);
    }
    red[t] = mx; __syncthreads();
    for (int s = 128; s > 0; s >>= 1) {
        if (t < s) red[t] = fmaxf(red[t], red[t + s]);
        __syncthreads();
    }
    mx = red[0];
    __syncthreads();

    float sum = 0.f;
    #pragma unroll
    for (int e = 0; e < 4; e++) {
        v[e] = __expf(v[e] - mx);   // padded lanes -> exp(-huge) = 0
        sum += v[e];
    }
    red[t] = sum; __syncthreads();
    for (int s = 128; s > 0; s >>= 1) {
        if (t < s) red[t] += red[t + s];
        __syncthreads();
    }
    float inv = 1.f / red[0];
    #pragma unroll
    for (int e = 0; e < 4; e++) {
        int i = t + e * 256;
        if (i < LP_) p[i] = v[e] * inv;
    }
}

// ---------------- sigmoid + deterministic per-batch sum --------------------
__global__ void sigmoid_sum_kernel(float* __restrict__ A, float* __restrict__ Asum)
{
    int b = blockIdx.x;
    float* p = A + (long long)b * LP_ * NC_;
    int t = threadIdx.x;  // 256
    float s = 0.f;
    for (int i = t; i < LP_ * NC_; i += 256) {
        float v = 1.f / (1.f + __expf(-p[i]));
        p[i] = v;
        s += v;
    }
    __shared__ float red[256];
    red[t] = s; __syncthreads();
    for (int st = 128; st > 0; st >>= 1) {
        if (t < st) red[t] += red[t + st];
        __syncthreads();
    }
    if (t == 0) Asum[b] = red[0];
}

// ---------------- tanh outer-product weighted reduction --------------------
// part[b][tile][d] = sum_{i in tile} sum_k tanh(pf[b,i,d]*cf[b,k,d]) * A[b,i,k]
__global__ void tanh_outer_kernel(const float* __restrict__ pf,
                                  const float* __restrict__ cf,
                                  const float* __restrict__ A,
                                  float* __restrict__ part)
{
    int b = blockIdx.y, tile = blockIdx.x;
    int d = threadIdx.x;  // 128
    __shared__ float cfs[NC_ * D_];  // 32 KB
    for (int i = threadIdx.x; i < NC_ * D_; i += 128)
        cfs[i] = cf[(long long)b * NC_ * D_ + i];
    __syncthreads();

    float acc = 0.f;
    int i0 = tile * ITILE_;
    for (int i = i0; i < i0 + ITILE_; i++) {
        float pv = pf[((long long)b * LP_ + i) * D_ + d];
        const float* Ar = A + ((long long)b * LP_ + i) * NC_;
        #pragma unroll 4
        for (int k = 0; k < NC_; k++) {
            float w = Ar[k];                        // broadcast, L1-cached
            float x = pv * cfs[k * D_ + d];
            float t = __expf(2.f * x);              // tanh = 1 - 2/(e^{2x}+1)
            float th = 1.f - __fdividef(2.f, t + 1.f);
            acc = fmaf(th, w, acc);
        }
    }
    part[((long long)b * NTILE_ + tile) * D_ + d] = acc;
}

__global__ void cp_reduce_kernel(const float* __restrict__ part,
                                 const float* __restrict__ Asum,
                                 float* __restrict__ cp)
{
    int b = blockIdx.x;
    int d = threadIdx.x;  // 128
    float s = 0.f;
    for (int t2 = 0; t2 < NTILE_; t2++)
        s += part[((long long)b * NTILE_ + t2) * D_ + d];
    cp[b * D_ + d] = s / Asum[b];
}

// ---------------- launch ----------------------------------------------------
static inline dim3 ggrid(int M, int N, int batch) {
    return dim3((N + 63) / 64, (M + 63) / 64, batch);
}

extern "C" void kernel_launch(void* const* d_in, const int* in_sizes, int n_in,
                              void* d_out, int out_size)
{
    const float* in_pe  = (const float*)d_in[0];   // [8,1000,320]
    const float* in_pfx = (const float*)d_in[1];   // [8,1000,128]
    const float* in_cf  = (const float*)d_in[2];   // [8,64,128]
    const float* emb_w = (const float*)d_in[3];  const float* emb_b = (const float*)d_in[4];
    const float* wq_w  = (const float*)d_in[5];  const float* wq_b  = (const float*)d_in[6];
    const float* wk_w  = (const float*)d_in[7];  const float* wk_b  = (const float*)d_in[8];
    const float* wv_w  = (const float*)d_in[9];  const float* wv_b  = (const float*)d_in[10];
    const float* wo_w  = (const float*)d_in[11]; const float* wo_b  = (const float*)d_in[12];
    const float* jp_w  = (const float*)d_in[13]; const float* jp_b  = (const float*)d_in[14];
    const float* jc_w  = (const float*)d_in[15]; const float* jc_b  = (const float*)d_in[16];
    const float* c1_w  = (const float*)d_in[17]; const float* c1_b  = (const float*)d_in[18];
    const float* c2_w  = (const float*)d_in[19]; const float* c2_b  = (const float*)d_in[20];
    const float* c3_w  = (const float*)d_in[21]; const float* c3_b  = (const float*)d_in[22];
    const float* c4_w  = (const float*)d_in[23]; const float* c4_b  = (const float*)d_in[24];

    float *pe, *Q, *K, *V, *pf, *P, *C, *S, *A, *Asum, *part, *cp, *h1, *h2, *h3;
    cudaGetSymbolAddress((void**)&pe,   g_pe);
    cudaGetSymbolAddress((void**)&Q,    g_Q);
    cudaGetSymbolAddress((void**)&K,    g_K);
    cudaGetSymbolAddress((void**)&V,    g_V);
    cudaGetSymbolAddress((void**)&pf,   g_pf);
    cudaGetSymbolAddress((void**)&P,    g_P);
    cudaGetSymbolAddress((void**)&C,    g_C);
    cudaGetSymbolAddress((void**)&S,    g_S);
    cudaGetSymbolAddress((void**)&A,    g_A);
    cudaGetSymbolAddress((void**)&Asum, g_Asum);
    cudaGetSymbolAddress((void**)&part, g_part);
    cudaGetSymbolAddress((void**)&cp,   g_cp);
    cudaGetSymbolAddress((void**)&h1,   g_h1);
    cudaGetSymbolAddress((void**)&h2,   g_h2);
    cudaGetSymbolAddress((void**)&h3,   g_h3);

    const int MALL = B_ * LP_;      // 8000
    const float inv_sqrt_d = 0.088388347648318440550f;  // 1/sqrt(128)

    // 1. pe = protein_embedding @ emb_w + emb_b
    gemm_kernel<false,false><<<ggrid(MALL,D_,1),256>>>(in_pe, emb_w, emb_b, pe,
        MALL, D_, E_, 0, 0, 0, 1.f);
    // 2-4. Q/K/V
    gemm_kernel<false,false><<<ggrid(MALL,D_,1),256>>>(pe, wq_w, wq_b, Q,
        MALL, D_, D_, 0, 0, 0, 1.f);
    gemm_kernel<false,false><<<ggrid(MALL,D_,1),256>>>(in_pfx, wk_w, wk_b, K,
        MALL, D_, D_, 0, 0, 0, 1.f);
    gemm_kernel<false,false><<<ggrid(MALL,D_,1),256>>>(in_pfx, wv_w, wv_b, V,
        MALL, D_, D_, 0, 0, 0, 1.f);
    // 5. S = Q @ K^T / sqrt(D), batched over B
    gemm_kernel<true,false><<<ggrid(LP_,LP_,B_),256>>>(Q, K, nullptr, S,
        LP_, LP_, D_, (long long)LP_*D_, (long long)LP_*D_, (long long)LP_*LP_, inv_sqrt_d);
    // 6. softmax rows
    softmax_kernel<<<B_*LP_,256>>>(S);
    // 7. AV = S @ V  (reuse pe buffer)
    gemm_kernel<false,false><<<ggrid(LP_,D_,B_),256>>>(S, V, nullptr, pe,
        LP_, D_, LP_, (long long)LP_*LP_, (long long)LP_*D_, (long long)LP_*D_, 1.f);
    // 8. protein_feats = AV @ wo + b
    gemm_kernel<false,false><<<ggrid(MALL,D_,1),256>>>(pe, wo_w, wo_b, pf,
        MALL, D_, D_, 0, 0, 0, 1.f);
    // 9. P = relu(pf) @ jp + b
    gemm_kernel<false,true><<<ggrid(MALL,D_,1),256>>>(pf, jp_w, jp_b, P,
        MALL, D_, D_, 0, 0, 0, 1.f);
    // 10. C = relu(cf) @ jc + b
    gemm_kernel<false,true><<<ggrid(B_*NC_,D_,1),256>>>(in_cf, jc_w, jc_b, C,
        B_*NC_, D_, D_, 0, 0, 0, 1.f);
    // 11. A_logits = P @ C^T, batched
    gemm_kernel<true,false><<<ggrid(LP_,NC_,B_),256>>>(P, C, nullptr, A,
        LP_, NC_, D_, (long long)LP_*D_, (long long)NC_*D_, (long long)LP_*NC_, 1.f);
    // 12. sigmoid + per-batch sum (deterministic)
    sigmoid_sum_kernel<<<B_,256>>>(A, Asum);
    // 13. tanh outer product weighted partial reduction
    tanh_outer_kernel<<<dim3(NTILE_,B_),128>>>(pf, in_cf, A, part);
    // 14. final reduce + normalize by Asum
    cp_reduce_kernel<<<B_,128>>>(part, Asum, cp);
    // 15-18. classifier MLP
    gemm_kernel<false,false><<<ggrid(B_,1024,1),256>>>(cp, c1_w, c1_b, h1,
        B_, 1024, D_, 0, 0, 0, 1.f);
    gemm_kernel<false,true><<<ggrid(B_,1024,1),256>>>(h1, c2_w, c2_b, h2,
        B_, 1024, 1024, 0, 0, 0, 1.f);
    gemm_kernel<false,true><<<ggrid(B_,256,1),256>>>(h2, c3_w, c3_b, h3,
        B_, 256, 1024, 0, 0, 0, 1.f);
    gemm_kernel<false,true><<<ggrid(B_,1,1),256>>>(h3, c4_w, c4_b, (float*)d_out,
        B_, 1, 256, 0, 0, 0, 1.f);
}

// round 2
// speedup vs baseline: 1.3412x; 1.3412x over previous
#include <cuda_runtime.h>
#include <math.h>
#include <stdint.h>

#define B_  8
#define LP_ 1000
#define NC_ 64
#define D_  128
#define E_  320
#define NTILE_ 100
#define ITILE_ 10

// ---------------- scratch (device globals; no allocation allowed) ----------
__device__ float g_pe [B_*LP_*D_];   // emb output; reused as attn@V output
__device__ float g_Q  [B_*LP_*D_];
__device__ float g_K  [B_*LP_*D_];
__device__ float g_V  [B_*LP_*D_];
__device__ float g_pf [B_*LP_*D_];   // protein_feats
__device__ float g_P  [B_*LP_*D_];
__device__ float g_C  [B_*NC_*D_];
__device__ float g_S  [B_*LP_*LP_];  // attention scores / probs (32 MB)
__device__ float g_A  [B_*LP_*NC_];  // sigmoid joint attention (unnormalized)
__device__ float g_Asum[B_];
__device__ float g_part[B_*NTILE_*D_];
__device__ float g_cp [B_*D_];
__device__ float g_h1 [B_*1024];
__device__ float g_h2 [B_*1024];
__device__ float g_h3 [B_*256];

// ---------------- tf32 MMA helpers -----------------------------------------
__device__ __forceinline__ uint32_t f2tf32(float x) {
    uint32_t r;
    asm("cvt.rna.tf32.f32 %0, %1;" : "=r"(r) : "f"(x));
    return r;
}
__device__ __forceinline__ void mma_tf32(float* d, const uint32_t* a, const uint32_t* b) {
    asm volatile(
        "mma.sync.aligned.m16n8k8.row.col.f32.tf32.tf32.f32 "
        "{%0,%1,%2,%3}, {%4,%5,%6,%7}, {%8,%9}, {%0,%1,%2,%3};\n"
        : "+f"(d[0]), "+f"(d[1]), "+f"(d[2]), "+f"(d[3])
        : "r"(a[0]), "r"(a[1]), "r"(a[2]), "r"(a[3]), "r"(b[0]), "r"(b[1]));
}

// ---------------- tf32 tensor-core GEMM (hi/lo split => ~fp32 accuracy) ----
// C[b] = alpha * act(A[b]) @ op(B[b]) + bias
// 64x64 block tile, BK=16, 8 warps (2M x 4N), warp tile 32x16.
// A smem: [m][k] stride 20 (conflict-free frag reads).
// B smem: TRANS_B -> [n][k] stride 20 ; else [k][n] stride 72.
template<bool TRANS_B, bool RELU_A>
__global__ void __launch_bounds__(256)
gemm_tf32(const float* __restrict__ A,
          const float* __restrict__ Bm,
          const float* __restrict__ bias,
          float* __restrict__ C,
          int M, int N, int K,
          long long sA, long long sB, long long sC,
          float alpha)
{
    __shared__ float As[64 * 20];
    __shared__ float Bs[1280];       // max(64*20, 16*72)

    int bz = blockIdx.z;
    A  += (long long)bz * sA;
    Bm += (long long)bz * sB;
    C  += (long long)bz * sC;
    int m0 = blockIdx.y * 64, n0 = blockIdx.x * 64;
    int t = threadIdx.x;
    int warp = t >> 5, lane = t & 31;
    int g = lane >> 2, l3 = lane & 3;
    int wm = (warp & 1) * 32;       // 2 warps along M
    int wn = (warp >> 1) * 16;      // 4 warps along N

    float acc[2][2][4];
    #pragma unroll
    for (int i = 0; i < 2; i++)
        #pragma unroll
        for (int j = 0; j < 2; j++)
            #pragma unroll
            for (int r = 0; r < 4; r++) acc[i][j][r] = 0.f;

    // gmem->smem load indices
    int arow = t >> 2, akq = (t & 3) * 4;        // A (and trans-B): row, k-quad

    for (int k0 = 0; k0 < K; k0 += 16) {
        // ---- A tile ----
        {
            int gm = m0 + arow, gk = k0 + akq;
            float4 v = make_float4(0.f, 0.f, 0.f, 0.f);
            if (gm < M && gk < K)
                v = *(const float4*)(A + (long long)gm * K + gk);
            if (RELU_A) {
                v.x = fmaxf(v.x, 0.f); v.y = fmaxf(v.y, 0.f);
                v.z = fmaxf(v.z, 0.f); v.w = fmaxf(v.w, 0.f);
            }
            *(float4*)&As[arow * 20 + akq] = v;
        }
        // ---- B tile ----
        if (TRANS_B) {
            int gn = n0 + arow, gk = k0 + akq;
            float4 v = make_float4(0.f, 0.f, 0.f, 0.f);
            if (gn < N && gk < K)
                v = *(const float4*)(Bm + (long long)gn * K + gk);
            *(float4*)&Bs[arow * 20 + akq] = v;
        } else {
            int kr = t >> 4, nq = (t & 15) * 4;
            int gk = k0 + kr, gn = n0 + nq;
            float4 v = make_float4(0.f, 0.f, 0.f, 0.f);
            if (gk < K && gn < N)
                v = *(const float4*)(Bm + (long long)gk * N + gn);
            *(float4*)&Bs[kr * 72 + nq] = v;
        }
        __syncthreads();

        #pragma unroll
        for (int ks = 0; ks < 2; ks++) {
            int kb = ks * 8 + l3;
            // A fragments (fp32 -> hi/lo tf32)
            uint32_t ahi[2][4], alo[2][4];
            #pragma unroll
            for (int mi = 0; mi < 2; mi++) {
                int rr = wm + mi * 16 + g;
                float a0 = As[rr * 20 + kb];
                float a1 = As[(rr + 8) * 20 + kb];
                float a2 = As[rr * 20 + kb + 4];
                float a3 = As[(rr + 8) * 20 + kb + 4];
                float f[4] = {a0, a1, a2, a3};
                #pragma unroll
                for (int r = 0; r < 4; r++) {
                    uint32_t h = f2tf32(f[r]);
                    ahi[mi][r] = h;
                    alo[mi][r] = f2tf32(f[r] - __uint_as_float(h));
                }
            }
            // B fragments
            uint32_t bhi[2][2], blo[2][2];
            #pragma unroll
            for (int ni = 0; ni < 2; ni++) {
                int cc = wn + ni * 8 + g;
                float b0, b1;
                if (TRANS_B) {
                    b0 = Bs[cc * 20 + kb];
                    b1 = Bs[cc * 20 + kb + 4];
                } else {
                    b0 = Bs[kb * 72 + cc];
                    b1 = Bs[(kb + 4) * 72 + cc];
                }
                uint32_t h0 = f2tf32(b0), h1 = f2tf32(b1);
                bhi[ni][0] = h0; bhi[ni][1] = h1;
                blo[ni][0] = f2tf32(b0 - __uint_as_float(h0));
                blo[ni][1] = f2tf32(b1 - __uint_as_float(h1));
            }
            // 3-term compensated MMA
            #pragma unroll
            for (int mi = 0; mi < 2; mi++)
                #pragma unroll
                for (int ni = 0; ni < 2; ni++) {
                    mma_tf32(acc[mi][ni], ahi[mi], bhi[ni]);
                    mma_tf32(acc[mi][ni], ahi[mi], blo[ni]);
                    mma_tf32(acc[mi][ni], alo[mi], bhi[ni]);
                }
        }
        __syncthreads();
    }

    // ---- epilogue ----
    #pragma unroll
    for (int mi = 0; mi < 2; mi++) {
        #pragma unroll
        for (int ni = 0; ni < 2; ni++) {
            int r0 = m0 + wm + mi * 16 + g;
            int c0 = n0 + wn + ni * 8 + 2 * l3;
            float* a4 = acc[mi][ni];
            float bv0 = 0.f, bv1 = 0.f;
            if (bias) {
                if (c0 < N)     bv0 = bias[c0];
                if (c0 + 1 < N) bv1 = bias[c0 + 1];
            }
            if (r0 < M) {
                if (c0 < N)     C[(long long)r0 * N + c0]     = a4[0] * alpha + bv0;
                if (c0 + 1 < N) C[(long long)r0 * N + c0 + 1] = a4[1] * alpha + bv1;
            }
            if (r0 + 8 < M) {
                if (c0 < N)     C[(long long)(r0 + 8) * N + c0]     = a4[2] * alpha + bv0;
                if (c0 + 1 < N) C[(long long)(r0 + 8) * N + c0 + 1] = a4[3] * alpha + bv1;
            }
        }
    }
}

// ---------------- fp32 fallback GEMM (tiny MLP layers) ---------------------
template<bool TRANS_B, bool RELU_A>
__global__ void gemm_kernel(const float* __restrict__ A,
                            const float* __restrict__ Bm,
                            const float* __restrict__ bias,
                            float* __restrict__ C,
                            int M, int N, int K,
                            long long sA, long long sB, long long sC,
                            float alpha)
{
    __shared__ float As[16][68];
    __shared__ float Bs[16][68];
    int bz = blockIdx.z;
    A  += (long long)bz * sA;
    Bm += (long long)bz * sB;
    C  += (long long)bz * sC;
    int m0 = blockIdx.y * 64, n0 = blockIdx.x * 64;
    int t  = threadIdx.x;
    int tx = t & 15, ty = t >> 4;

    float acc[4][4] = {};

    for (int k0 = 0; k0 < K; k0 += 16) {
        #pragma unroll
        for (int e = 0; e < 4; e++) {
            int idx = t + e * 256;
            int kk = idx & 15, mm = idx >> 4;
            int gm = m0 + mm, gk = k0 + kk;
            float v = 0.f;
            if (gm < M && gk < K) v = A[(long long)gm * K + gk];
            if (RELU_A) v = fmaxf(v, 0.f);
            As[kk][mm] = v;
        }
        #pragma unroll
        for (int e = 0; e < 4; e++) {
            int idx = t + e * 256;
            if (TRANS_B) {
                int kk = idx & 15, nn = idx >> 4;
                int gn = n0 + nn, gk = k0 + kk;
                float v = 0.f;
                if (gn < N && gk < K) v = Bm[(long long)gn * K + gk];
                Bs[kk][nn] = v;
            } else {
                int nn = idx & 63, kk = idx >> 6;
                int gn = n0 + nn, gk = k0 + kk;
                float v = 0.f;
                if (gk < K && gn < N) v = Bm[(long long)gk * N + gn];
                Bs[kk][nn] = v;
            }
        }
        __syncthreads();
        #pragma unroll
        for (int kk = 0; kk < 16; kk++) {
            float a[4], b[4];
            #pragma unroll
            for (int i = 0; i < 4; i++) a[i] = As[kk][ty * 4 + i];
            #pragma unroll
            for (int j = 0; j < 4; j++) b[j] = Bs[kk][tx * 4 + j];
            #pragma unroll
            for (int i = 0; i < 4; i++)
                #pragma unroll
                for (int j = 0; j < 4; j++)
                    acc[i][j] = fmaf(a[i], b[j], acc[i][j]);
        }
        __syncthreads();
    }

    #pragma unroll
    for (int i = 0; i < 4; i++) {
        int gm = m0 + ty * 4 + i;
        if (gm >= M) continue;
        #pragma unroll
        for (int j = 0; j < 4; j++) {
            int gn = n0 + tx * 4 + j;
            if (gn >= N) continue;
            float v = acc[i][j] * alpha;
            if (bias) v += bias[gn];
            C[(long long)gm * N + gn] = v;
        }
    }
}

// ---------------- row softmax (register-resident, LP=1000) -----------------
__global__ void softmax_kernel(float* __restrict__ S)
{
    long long row = blockIdx.x;
    float* p = S + row * LP_;
    int t = threadIdx.x;  // 256
    __shared__ float red[256];

    float v[4];
    float mx = -1e30f;
    #pragma unroll
    for (int e = 0; e < 4; e++) {
        int i = t + e * 256;
        v[e] = (i < LP_) ? p[i] : -1e30f;
        mx = fmaxf(mx, v[e]);
    }
    red[t] = mx; __syncthreads();
    for (int s = 128; s > 0; s >>= 1) {
        if (t < s) red[t] = fmaxf(red[t], red[t + s]);
        __syncthreads();
    }
    mx = red[0];
    __syncthreads();

    float sum = 0.f;
    #pragma unroll
    for (int e = 0; e < 4; e++) {
        v[e] = __expf(v[e] - mx);
        sum += v[e];
    }
    red[t] = sum; __syncthreads();
    for (int s = 128; s > 0; s >>= 1) {
        if (t < s) red[t] += red[t + s];
        __syncthreads();
    }
    float inv = 1.f / red[0];
    #pragma unroll
    for (int e = 0; e < 4; e++) {
        int i = t + e * 256;
        if (i < LP_) p[i] = v[e] * inv;
    }
}

// ---------------- sigmoid + deterministic per-batch sum --------------------
__global__ void sigmoid_sum_kernel(float* __restrict__ A, float* __restrict__ Asum)
{
    int b = blockIdx.x;
    float* p = A + (long long)b * LP_ * NC_;
    int t = threadIdx.x;  // 1024
    float s = 0.f;
    for (int i = t; i < LP_ * NC_; i += 1024) {
        float v = 1.f / (1.f + __expf(-p[i]));
        p[i] = v;
        s += v;
    }
    __shared__ float red[1024];
    red[t] = s; __syncthreads();
    for (int st = 512; st > 0; st >>= 1) {
        if (t < st) red[t] += red[t + st];
        __syncthreads();
    }
    if (t == 0) Asum[b] = red[0];
}

// ---------------- tanh outer-product weighted reduction --------------------
__global__ void tanh_outer_kernel(const float* __restrict__ pf,
                                  const float* __restrict__ cf,
                                  const float* __restrict__ A,
                                  float* __restrict__ part)
{
    int b = blockIdx.y, tile = blockIdx.x;
    int d = threadIdx.x;  // 128
    __shared__ float cfs[NC_ * D_];  // 32 KB
    for (int i = threadIdx.x; i < NC_ * D_; i += 128)
        cfs[i] = cf[(long long)b * NC_ * D_ + i];
    __syncthreads();

    float acc = 0.f;
    int i0 = tile * ITILE_;
    for (int i = i0; i < i0 + ITILE_; i++) {
        float pv = pf[((long long)b * LP_ + i) * D_ + d];
        const float* Ar = A + ((long long)b * LP_ + i) * NC_;
        #pragma unroll 4
        for (int k = 0; k < NC_; k++) {
            float w = Ar[k];
            float x = pv * cfs[k * D_ + d];
            float t = __expf(2.f * x);              // tanh = 1 - 2/(e^{2x}+1)
            float th = 1.f - __fdividef(2.f, t + 1.f);
            acc = fmaf(th, w, acc);
        }
    }
    part[((long long)b * NTILE_ + tile) * D_ + d] = acc;
}

__global__ void cp_reduce_kernel(const float* __restrict__ part,
                                 const float* __restrict__ Asum,
                                 float* __restrict__ cp)
{
    int b = blockIdx.x;
    int d = threadIdx.x;  // 128
    float s = 0.f;
    for (int t2 = 0; t2 < NTILE_; t2++)
        s += part[((long long)b * NTILE_ + t2) * D_ + d];
    cp[b * D_ + d] = s / Asum[b];
}

// ---------------- launch ----------------------------------------------------
static inline dim3 ggrid(int M, int N, int batch) {
    return dim3((N + 63) / 64, (M + 63) / 64, batch);
}

extern "C" void kernel_launch(void* const* d_in, const int* in_sizes, int n_in,
                              void* d_out, int out_size)
{
    const float* in_pe  = (const float*)d_in[0];   // [8,1000,320]
    const float* in_pfx = (const float*)d_in[1];   // [8,1000,128]
    const float* in_cf  = (const float*)d_in[2];   // [8,64,128]
    const float* emb_w = (const float*)d_in[3];  const float* emb_b = (const float*)d_in[4];
    const float* wq_w  = (const float*)d_in[5];  const float* wq_b  = (const float*)d_in[6];
    const float* wk_w  = (const float*)d_in[7];  const float* wk_b  = (const float*)d_in[8];
    const float* wv_w  = (const float*)d_in[9];  const float* wv_b  = (const float*)d_in[10];
    const float* wo_w  = (const float*)d_in[11]; const float* wo_b  = (const float*)d_in[12];
    const float* jp_w  = (const float*)d_in[13]; const float* jp_b  = (const float*)d_in[14];
    const float* jc_w  = (const float*)d_in[15]; const float* jc_b  = (const float*)d_in[16];
    const float* c1_w  = (const float*)d_in[17]; const float* c1_b  = (const float*)d_in[18];
    const float* c2_w  = (const float*)d_in[19]; const float* c2_b  = (const float*)d_in[20];
    const float* c3_w  = (const float*)d_in[21]; const float* c3_b  = (const float*)d_in[22];
    const float* c4_w  = (const float*)d_in[23]; const float* c4_b  = (const float*)d_in[24];

    float *pe, *Q, *K, *V, *pf, *P, *C, *S, *A, *Asum, *part, *cp, *h1, *h2, *h3;
    cudaGetSymbolAddress((void**)&pe,   g_pe);
    cudaGetSymbolAddress((void**)&Q,    g_Q);
    cudaGetSymbolAddress((void**)&K,    g_K);
    cudaGetSymbolAddress((void**)&V,    g_V);
    cudaGetSymbolAddress((void**)&pf,   g_pf);
    cudaGetSymbolAddress((void**)&P,    g_P);
    cudaGetSymbolAddress((void**)&C,    g_C);
    cudaGetSymbolAddress((void**)&S,    g_S);
    cudaGetSymbolAddress((void**)&A,    g_A);
    cudaGetSymbolAddress((void**)&Asum, g_Asum);
    cudaGetSymbolAddress((void**)&part, g_part);
    cudaGetSymbolAddress((void**)&cp,   g_cp);
    cudaGetSymbolAddress((void**)&h1,   g_h1);
    cudaGetSymbolAddress((void**)&h2,   g_h2);
    cudaGetSymbolAddress((void**)&h3,   g_h3);

    const int MALL = B_ * LP_;      // 8000
    const float inv_sqrt_d = 0.088388347648318440550f;  // 1/sqrt(128)

    // 1. pe = protein_embedding @ emb_w + emb_b
    gemm_tf32<false,false><<<ggrid(MALL,D_,1),256>>>(in_pe, emb_w, emb_b, pe,
        MALL, D_, E_, 0, 0, 0, 1.f);
    // 2-4. Q/K/V
    gemm_tf32<false,false><<<ggrid(MALL,D_,1),256>>>(pe, wq_w, wq_b, Q,
        MALL, D_, D_, 0, 0, 0, 1.f);
    gemm_tf32<false,false><<<ggrid(MALL,D_,1),256>>>(in_pfx, wk_w, wk_b, K,
        MALL, D_, D_, 0, 0, 0, 1.f);
    gemm_tf32<false,false><<<ggrid(MALL,D_,1),256>>>(in_pfx, wv_w, wv_b, V,
        MALL, D_, D_, 0, 0, 0, 1.f);
    // 5. S = Q @ K^T / sqrt(D), batched over B
    gemm_tf32<true,false><<<ggrid(LP_,LP_,B_),256>>>(Q, K, nullptr, S,
        LP_, LP_, D_, (long long)LP_*D_, (long long)LP_*D_, (long long)LP_*LP_, inv_sqrt_d);
    // 6. softmax rows
    softmax_kernel<<<B_*LP_,256>>>(S);
    // 7. AV = S @ V  (reuse pe buffer)
    gemm_tf32<false,false><<<ggrid(LP_,D_,B_),256>>>(S, V, nullptr, pe,
        LP_, D_, LP_, (long long)LP_*LP_, (long long)LP_*D_, (long long)LP_*D_, 1.f);
    // 8. protein_feats = AV @ wo + b
    gemm_tf32<false,false><<<ggrid(MALL,D_,1),256>>>(pe, wo_w, wo_b, pf,
        MALL, D_, D_, 0, 0, 0, 1.f);
    // 9. P = relu(pf) @ jp + b
    gemm_tf32<false,true><<<ggrid(MALL,D_,1),256>>>(pf, jp_w, jp_b, P,
        MALL, D_, D_, 0, 0, 0, 1.f);
    // 10. C = relu(cf) @ jc + b
    gemm_tf32<false,true><<<ggrid(B_*NC_,D_,1),256>>>(in_cf, jc_w, jc_b, C,
        B_*NC_, D_, D_, 0, 0, 0, 1.f);
    // 11. A_logits = P @ C^T, batched
    gemm_tf32<true,false><<<ggrid(LP_,NC_,B_),256>>>(P, C, nullptr, A,
        LP_, NC_, D_, (long long)LP_*D_, (long long)NC_*D_, (long long)LP_*NC_, 1.f);
    // 12. sigmoid + per-batch sum (deterministic)
    sigmoid_sum_kernel<<<B_,1024>>>(A, Asum);
    // 13. tanh outer product weighted partial reduction
    tanh_outer_kernel<<<dim3(NTILE_,B_),128>>>(pf, in_cf, A, part);
    // 14. final reduce + normalize by Asum
    cp_reduce_kernel<<<B_,128>>>(part, Asum, cp);
    // 15-18. classifier MLP (tiny, fp32)
    gemm_kernel<false,false><<<ggrid(B_,1024,1),256>>>(cp, c1_w, c1_b, h1,
        B_, 1024, D_, 0, 0, 0, 1.f);
    gemm_kernel<false,true><<<ggrid(B_,1024,1),256>>>(h1, c2_w, c2_b, h2,
        B_, 1024, 1024, 0, 0, 0, 1.f);
    gemm_kernel<false,true><<<ggrid(B_,256,1),256>>>(h2, c3_w, c3_b, h3,
        B_, 256, 1024, 0, 0, 0, 1.f);
    gemm_kernel<false,true><<<ggrid(B_,1,1),256>>>(h3, c4_w, c4_b, (float*)d_out,
        B_, 1, 256, 0, 0, 0, 1.f);
}

// round 3
// speedup vs baseline: 1.8381x; 1.3705x over previous
#include <cuda_runtime.h>
#include <math.h>
#include <stdint.h>

#define B_  8
#define LP_ 1000
#define NC_ 64
#define D_  128
#define E_  320
#define NTILE_ 100
#define ITILE_ 10

// ---------------- scratch (device globals) ----------------------------------
__device__ float g_Q  [B_*LP_*D_];
__device__ float g_K  [B_*LP_*D_];
__device__ float g_V  [B_*LP_*D_];
__device__ float g_AV [B_*LP_*D_];
__device__ float g_pf [B_*LP_*D_];
__device__ float g_P  [B_*LP_*D_];
__device__ float g_C  [B_*NC_*D_];
__device__ float g_S  [B_*LP_*LP_];
__device__ float g_A  [B_*LP_*NC_];
__device__ float g_Wq [E_*D_];
__device__ float g_bq [D_];
__device__ float g_Apart[B_*8];
__device__ float g_part[B_*NTILE_*D_];
__device__ float g_cp [B_*D_];
__device__ float g_h1 [B_*1024];
__device__ float g_h2 [B_*1024];
__device__ float g_h3 [B_*256];

// ---------------- tf32 helpers ----------------------------------------------
__device__ __forceinline__ uint32_t f2tf32(float x) {
    uint32_t r;
    asm("cvt.rna.tf32.f32 %0, %1;" : "=r"(r) : "f"(x));
    return r;
}
__device__ __forceinline__ void mma_tf32(float* d, const uint32_t* a, const uint32_t* b) {
    asm volatile(
        "mma.sync.aligned.m16n8k8.row.col.f32.tf32.tf32.f32 "
        "{%0,%1,%2,%3}, {%4,%5,%6,%7}, {%8,%9}, {%0,%1,%2,%3};\n"
        : "+f"(d[0]), "+f"(d[1]), "+f"(d[2]), "+f"(d[3])
        : "r"(a[0]), "r"(a[1]), "r"(a[2]), "r"(a[3]), "r"(b[0]), "r"(b[1]));
}
// convert float4 -> 4x(hi,lo) tf32 pairs, store as 2 uint4 (idx must be even)
__device__ __forceinline__ void cvt_store(uint2* base, int idx, float4 v) {
    uint32_t h0 = f2tf32(v.x), h1 = f2tf32(v.y), h2 = f2tf32(v.z), h3 = f2tf32(v.w);
    uint4 p0 = make_uint4(h0, f2tf32(v.x - __uint_as_float(h0)),
                          h1, f2tf32(v.y - __uint_as_float(h1)));
    uint4 p1 = make_uint4(h2, f2tf32(v.z - __uint_as_float(h2)),
                          h3, f2tf32(v.w - __uint_as_float(h3)));
    *(uint4*)(base + idx)     = p0;
    *(uint4*)(base + idx + 2) = p1;
}

// ---------------- tf32 tensor-core GEMM v2 -----------------------------------
// 64x64 tile, BK=16, 256 threads (8 warps, 2M x 4N, warp tile 32x16).
// smem: interleaved (hi,lo) uint2. A: [m][k] pitch 20; B trans: [n][k] pitch 20;
// B non-trans: [k][n] pitch 68.  (pitch % 16 == 4 in 8B units => conflict-free frags)
// Register double-buffering of gmem loads; 3xTF32 compensation (~fp32 accuracy).
template<bool TRANS_B, bool RELU_A>
__global__ void __launch_bounds__(256)
gemm_tf32(const float* __restrict__ A,
          const float* __restrict__ Bm,
          const float* __restrict__ bias,
          float* __restrict__ C,
          int M, int N, int K,
          long long sA, long long sB, long long sC,
          float alpha)
{
    __shared__ __align__(16) uint2 As[2][64 * 20];
    __shared__ __align__(16) uint2 Bs[2][64 * 20];

    int bz = blockIdx.z;
    A  += (long long)bz * sA;
    Bm += (long long)bz * sB;
    C  += (long long)bz * sC;
    int m0 = blockIdx.y * 64, n0 = blockIdx.x * 64;
    int t = threadIdx.x, warp = t >> 5, lane = t & 31;
    int g = lane >> 2, l3 = lane & 3;
    int wm = (warp & 1) * 32;
    int wn = (warp >> 1) * 16;

    float acc[2][2][4];
    #pragma unroll
    for (int i = 0; i < 2; i++)
        #pragma unroll
        for (int j = 0; j < 2; j++)
            #pragma unroll
            for (int r = 0; r < 4; r++) acc[i][j][r] = 0.f;

    int arow = t >> 2, akq = (t & 3) * 4;     // A / trans-B loader
    int bk   = t >> 4, bnq = (t & 15) * 4;    // non-trans B loader

    int kt = (K + 15) >> 4;
    float4 ra, rb;

    // ---- prologue: load+convert tile 0 into stage 0 ----
    {
        int gm = m0 + arow, gk = akq;
        ra = make_float4(0.f, 0.f, 0.f, 0.f);
        if (gm < M && gk < K) ra = *(const float4*)(A + (long long)gm * K + gk);
        if (RELU_A) { ra.x = fmaxf(ra.x, 0.f); ra.y = fmaxf(ra.y, 0.f);
                      ra.z = fmaxf(ra.z, 0.f); ra.w = fmaxf(ra.w, 0.f); }
        rb = make_float4(0.f, 0.f, 0.f, 0.f);
        if (TRANS_B) {
            int gn = n0 + arow;
            if (gn < N && gk < K) rb = *(const float4*)(Bm + (long long)gn * K + gk);
        } else {
            int gk2 = bk, gn = n0 + bnq;
            if (gk2 < K && gn < N) rb = *(const float4*)(Bm + (long long)gk2 * N + gn);
        }
        cvt_store(As[0], arow * 20 + akq, ra);
        if (TRANS_B) cvt_store(Bs[0], arow * 20 + akq, rb);
        else         cvt_store(Bs[0], bk * 68 + bnq, rb);
    }
    __syncthreads();

    for (int it = 0; it < kt; it++) {
        int s = it & 1;
        // ---- prefetch next k-tile into registers ----
        if (it + 1 < kt) {
            int k0 = (it + 1) << 4;
            int gm = m0 + arow, gk = k0 + akq;
            ra = make_float4(0.f, 0.f, 0.f, 0.f);
            if (gm < M && gk < K) ra = *(const float4*)(A + (long long)gm * K + gk);
            if (RELU_A) { ra.x = fmaxf(ra.x, 0.f); ra.y = fmaxf(ra.y, 0.f);
                          ra.z = fmaxf(ra.z, 0.f); ra.w = fmaxf(ra.w, 0.f); }
            rb = make_float4(0.f, 0.f, 0.f, 0.f);
            if (TRANS_B) {
                int gn = n0 + arow;
                if (gn < N && gk < K) rb = *(const float4*)(Bm + (long long)gn * K + gk);
            } else {
                int gk2 = k0 + bk, gn = n0 + bnq;
                if (gk2 < K && gn < N) rb = *(const float4*)(Bm + (long long)gk2 * N + gn);
            }
        }
        // ---- compute on stage s ----
        #pragma unroll
        for (int ks = 0; ks < 2; ks++) {
            int kb = ks * 8 + l3;
            uint32_t ahi[2][4], alo[2][4];
            #pragma unroll
            for (int mi = 0; mi < 2; mi++) {
                int rr = wm + mi * 16 + g;
                uint2 x0 = As[s][rr * 20 + kb];
                uint2 x1 = As[s][(rr + 8) * 20 + kb];
                uint2 x2 = As[s][rr * 20 + kb + 4];
                uint2 x3 = As[s][(rr + 8) * 20 + kb + 4];
                ahi[mi][0] = x0.x; alo[mi][0] = x0.y;
                ahi[mi][1] = x1.x; alo[mi][1] = x1.y;
                ahi[mi][2] = x2.x; alo[mi][2] = x2.y;
                ahi[mi][3] = x3.x; alo[mi][3] = x3.y;
            }
            uint32_t bhi[2][2], blo[2][2];
            #pragma unroll
            for (int ni = 0; ni < 2; ni++) {
                int cc = wn + ni * 8 + g;
                uint2 y0 = TRANS_B ? Bs[s][cc * 20 + kb]     : Bs[s][kb * 68 + cc];
                uint2 y1 = TRANS_B ? Bs[s][cc * 20 + kb + 4] : Bs[s][(kb + 4) * 68 + cc];
                bhi[ni][0] = y0.x; blo[ni][0] = y0.y;
                bhi[ni][1] = y1.x; blo[ni][1] = y1.y;
            }
            #pragma unroll
            for (int mi = 0; mi < 2; mi++)
                #pragma unroll
                for (int ni = 0; ni < 2; ni++) {
                    mma_tf32(acc[mi][ni], ahi[mi], bhi[ni]);
                    mma_tf32(acc[mi][ni], ahi[mi], blo[ni]);
                    mma_tf32(acc[mi][ni], alo[mi], bhi[ni]);
                }
        }
        // ---- store prefetched tile into other stage ----
        if (it + 1 < kt) {
            cvt_store(As[s ^ 1], arow * 20 + akq, ra);
            if (TRANS_B) cvt_store(Bs[s ^ 1], arow * 20 + akq, rb);
            else         cvt_store(Bs[s ^ 1], bk * 68 + bnq, rb);
        }
        __syncthreads();
    }

    // ---- epilogue (N always even here) ----
    #pragma unroll
    for (int mi = 0; mi < 2; mi++)
        #pragma unroll
        for (int ni = 0; ni < 2; ni++) {
            int r0 = m0 + wm + mi * 16 + g;
            int c0 = n0 + wn + ni * 8 + 2 * l3;
            if (c0 >= N) continue;
            float b0 = 0.f, b1 = 0.f;
            if (bias) { b0 = bias[c0]; b1 = bias[c0 + 1]; }
            if (r0 < M) {
                float2 v = make_float2(acc[mi][ni][0] * alpha + b0,
                                       acc[mi][ni][1] * alpha + b1);
                *(float2*)(C + (long long)r0 * N + c0) = v;
            }
            if (r0 + 8 < M) {
                float2 v = make_float2(acc[mi][ni][2] * alpha + b0,
                                       acc[mi][ni][3] * alpha + b1);
                *(float2*)(C + (long long)(r0 + 8) * N + c0) = v;
            }
        }
}

// ---------------- bq' = emb_b @ wq_w + wq_b ---------------------------------
__global__ void fuse_bq_kernel(const float* __restrict__ emb_b,
                               const float* __restrict__ wq_w,
                               const float* __restrict__ wq_b,
                               float* __restrict__ bq)
{
    int n = threadIdx.x;  // 128
    float s = wq_b[n];
    for (int k = 0; k < D_; k++) s = fmaf(emb_b[k], wq_w[k * D_ + n], s);
    bq[n] = s;
}

// ---------------- row softmax -------------------------------------------------
__global__ void softmax_kernel(float* __restrict__ S)
{
    long long row = blockIdx.x;
    float* p = S + row * LP_;
    int t = threadIdx.x;  // 256
    __shared__ float red[256];

    float v[4];
    float mx = -1e30f;
    #pragma unroll
    for (int e = 0; e < 4; e++) {
        int i = t + e * 256;
        v[e] = (i < LP_) ? p[i] : -1e30f;
        mx = fmaxf(mx, v[e]);
    }
    red[t] = mx; __syncthreads();
    for (int s = 128; s > 0; s >>= 1) {
        if (t < s) red[t] = fmaxf(red[t], red[t + s]);
        __syncthreads();
    }
    mx = red[0];
    __syncthreads();
    float sum = 0.f;
    #pragma unroll
    for (int e = 0; e < 4; e++) { v[e] = __expf(v[e] - mx); sum += v[e]; }
    red[t] = sum; __syncthreads();
    for (int s = 128; s > 0; s >>= 1) {
        if (t < s) red[t] += red[t + s];
        __syncthreads();
    }
    float inv = 1.f / red[0];
    #pragma unroll
    for (int e = 0; e < 4; e++) {
        int i = t + e * 256;
        if (i < LP_) p[i] = v[e] * inv;
    }
}

// ---------------- sigmoid + partial sums (deterministic) --------------------
__global__ void sigmoid_kernel(float* __restrict__ A, float* __restrict__ Apart)
{
    int b = blockIdx.x, seg = blockIdx.y, t = threadIdx.x;  // 256
    float* p = A + (long long)b * LP_ * NC_ + seg * 8000;
    float s = 0.f;
    for (int i = t; i < 8000; i += 256) {
        float v = 1.f / (1.f + __expf(-p[i]));
        p[i] = v;
        s += v;
    }
    __shared__ float red[256];
    red[t] = s; __syncthreads();
    for (int st = 128; st > 0; st >>= 1) {
        if (t < st) red[t] += red[t + st];
        __syncthreads();
    }
    if (t == 0) Apart[b * 8 + seg] = red[0];
}

// ---------------- tanh outer-product weighted reduction ---------------------
__global__ void tanh_outer_kernel(const float* __restrict__ pf,
                                  const float* __restrict__ cf,
                                  const float* __restrict__ A,
                                  float* __restrict__ part)
{
    int b = blockIdx.y, tile = blockIdx.x;
    int d = threadIdx.x;  // 128
    __shared__ float cfs[NC_ * D_];
    for (int i = threadIdx.x; i < NC_ * D_; i += 128)
        cfs[i] = cf[(long long)b * NC_ * D_ + i];
    __syncthreads();

    float acc = 0.f;
    int i0 = tile * ITILE_;
    for (int i = i0; i < i0 + ITILE_; i++) {
        float pv = pf[((long long)b * LP_ + i) * D_ + d];
        const float* Ar = A + ((long long)b * LP_ + i) * NC_;
        #pragma unroll 4
        for (int k = 0; k < NC_; k++) {
            float w = Ar[k];
            float x = pv * cfs[k * D_ + d];
            float th;
            asm("tanh.approx.f32 %0, %1;" : "=f"(th) : "f"(x));
            acc = fmaf(th, w, acc);
        }
    }
    part[((long long)b * NTILE_ + tile) * D_ + d] = acc;
}

__global__ void cp_reduce_kernel(const float* __restrict__ part,
                                 const float* __restrict__ Apart,
                                 float* __restrict__ cp)
{
    int b = blockIdx.x;
    int d = threadIdx.x;  // 128
    float as = 0.f;
    #pragma unroll
    for (int j = 0; j < 8; j++) as += Apart[b * 8 + j];
    float s = 0.f;
    for (int t2 = 0; t2 < NTILE_; t2++)
        s += part[((long long)b * NTILE_ + t2) * D_ + d];
    cp[b * D_ + d] = s / as;
}

// ---------------- skinny GEMM (M = 8 rows) -----------------------------------
// grid = ceil(N/32); 256 threads: lane group = n, warp-slice = k segment.
template<bool RELU_OUT>
__global__ void __launch_bounds__(256)
skinny_gemm(const float* __restrict__ A, const float* __restrict__ W,
            const float* __restrict__ bias, float* __restrict__ C,
            int N, int K)
{
    __shared__ float As[8 * 1024];
    __shared__ float red[8][8][32];
    int t = threadIdx.x;
    for (int i = t; i < 8 * K; i += 256) As[i] = A[i];
    __syncthreads();

    int n = blockIdx.x * 32 + (t & 31);
    int ks = t >> 5;
    int kseg = K >> 3;
    float acc[8] = {};
    if (n < N) {
        for (int k = ks * kseg; k < (ks + 1) * kseg; k++) {
            float w = W[(long long)k * N + n];
            #pragma unroll
            for (int m = 0; m < 8; m++) acc[m] = fmaf(As[m * K + k], w, acc[m]);
        }
    }
    #pragma unroll
    for (int m = 0; m < 8; m++) red[ks][m][t & 31] = acc[m];
    __syncthreads();

    int m = t >> 5, ln = t & 31;
    int nn = blockIdx.x * 32 + ln;
    if (nn < N) {
        float s = 0.f;
        #pragma unroll
        for (int j = 0; j < 8; j++) s += red[j][m][ln];
        s += bias[nn];
        if (RELU_OUT) s = fmaxf(s, 0.f);
        C[(long long)m * N + nn] = s;
    }
}

// ---------------- launch ------------------------------------------------------
static inline dim3 ggrid(int M, int N, int batch) {
    return dim3((N + 63) / 64, (M + 63) / 64, batch);
}

extern "C" void kernel_launch(void* const* d_in, const int* in_sizes, int n_in,
                              void* d_out, int out_size)
{
    const float* in_pe  = (const float*)d_in[0];   // [8,1000,320]
    const float* in_pfx = (const float*)d_in[1];   // [8,1000,128]
    const float* in_cf  = (const float*)d_in[2];   // [8,64,128]
    const float* emb_w = (const float*)d_in[3];  const float* emb_b = (const float*)d_in[4];
    const float* wq_w  = (const float*)d_in[5];  const float* wq_b  = (const float*)d_in[6];
    const float* wk_w  = (const float*)d_in[7];  const float* wk_b  = (const float*)d_in[8];
    const float* wv_w  = (const float*)d_in[9];  const float* wv_b  = (const float*)d_in[10];
    const float* wo_w  = (const float*)d_in[11]; const float* wo_b  = (const float*)d_in[12];
    const float* jp_w  = (const float*)d_in[13]; const float* jp_b  = (const float*)d_in[14];
    const float* jc_w  = (const float*)d_in[15]; const float* jc_b  = (const float*)d_in[16];
    const float* c1_w  = (const float*)d_in[17]; const float* c1_b  = (const float*)d_in[18];
    const float* c2_w  = (const float*)d_in[19]; const float* c2_b  = (const float*)d_in[20];
    const float* c3_w  = (const float*)d_in[21]; const float* c3_b  = (const float*)d_in[22];
    const float* c4_w  = (const float*)d_in[23]; const float* c4_b  = (const float*)d_in[24];

    float *Q, *K, *V, *AV, *pf, *P, *C, *S, *A, *Wq, *bq, *Apart, *part, *cp, *h1, *h2, *h3;
    cudaGetSymbolAddress((void**)&Q,    g_Q);
    cudaGetSymbolAddress((void**)&K,    g_K);
    cudaGetSymbolAddress((void**)&V,    g_V);
    cudaGetSymbolAddress((void**)&AV,   g_AV);
    cudaGetSymbolAddress((void**)&pf,   g_pf);
    cudaGetSymbolAddress((void**)&P,    g_P);
    cudaGetSymbolAddress((void**)&C,    g_C);
    cudaGetSymbolAddress((void**)&S,    g_S);
    cudaGetSymbolAddress((void**)&A,    g_A);
    cudaGetSymbolAddress((void**)&Wq,   g_Wq);
    cudaGetSymbolAddress((void**)&bq,   g_bq);
    cudaGetSymbolAddress((void**)&Apart,g_Apart);
    cudaGetSymbolAddress((void**)&part, g_part);
    cudaGetSymbolAddress((void**)&cp,   g_cp);
    cudaGetSymbolAddress((void**)&h1,   g_h1);
    cudaGetSymbolAddress((void**)&h2,   g_h2);
    cudaGetSymbolAddress((void**)&h3,   g_h3);

    const int MALL = B_ * LP_;      // 8000
    const float inv_sqrt_d = 0.088388347648318440550f;  // 1/sqrt(128)

    // 0a. Wq' = emb_w @ wq_w   [320x128]
    gemm_tf32<false,false><<<ggrid(E_,D_,1),256>>>(emb_w, wq_w, nullptr, Wq,
        E_, D_, D_, 0, 0, 0, 1.f);
    // 0b. bq' = emb_b @ wq_w + wq_b
    fuse_bq_kernel<<<1,128>>>(emb_b, wq_w, wq_b, bq);
    // 1. Q = X @ Wq' + bq'   (emb+Q folded)
    gemm_tf32<false,false><<<ggrid(MALL,D_,1),256>>>(in_pe, Wq, bq, Q,
        MALL, D_, E_, 0, 0, 0, 1.f);
    // 2-3. K, V
    gemm_tf32<false,false><<<ggrid(MALL,D_,1),256>>>(in_pfx, wk_w, wk_b, K,
        MALL, D_, D_, 0, 0, 0, 1.f);
    gemm_tf32<false,false><<<ggrid(MALL,D_,1),256>>>(in_pfx, wv_w, wv_b, V,
        MALL, D_, D_, 0, 0, 0, 1.f);
    // 4. S = Q @ K^T / sqrt(D)
    gemm_tf32<true,false><<<ggrid(LP_,LP_,B_),256>>>(Q, K, nullptr, S,
        LP_, LP_, D_, (long long)LP_*D_, (long long)LP_*D_, (long long)LP_*LP_, inv_sqrt_d);
    // 5. softmax
    softmax_kernel<<<B_*LP_,256>>>(S);
    // 6. AV = S @ V
    gemm_tf32<false,false><<<ggrid(LP_,D_,B_),256>>>(S, V, nullptr, AV,
        LP_, D_, LP_, (long long)LP_*LP_, (long long)LP_*D_, (long long)LP_*D_, 1.f);
    // 7. pf = AV @ wo + b
    gemm_tf32<false,false><<<ggrid(MALL,D_,1),256>>>(AV, wo_w, wo_b, pf,
        MALL, D_, D_, 0, 0, 0, 1.f);
    // 8. P = relu(pf) @ jp + b
    gemm_tf32<false,true><<<ggrid(MALL,D_,1),256>>>(pf, jp_w, jp_b, P,
        MALL, D_, D_, 0, 0, 0, 1.f);
    // 9. C = relu(cf) @ jc + b
    gemm_tf32<false,true><<<ggrid(B_*NC_,D_,1),256>>>(in_cf, jc_w, jc_b, C,
        B_*NC_, D_, D_, 0, 0, 0, 1.f);
    // 10. A_logits = P @ C^T
    gemm_tf32<true,false><<<ggrid(LP_,NC_,B_),256>>>(P, C, nullptr, A,
        LP_, NC_, D_, (long long)LP_*D_, (long long)NC_*D_, (long long)LP_*NC_, 1.f);
    // 11. sigmoid + partial sums
    sigmoid_kernel<<<dim3(B_,8),256>>>(A, Apart);
    // 12. tanh outer product partials
    tanh_outer_kernel<<<dim3(NTILE_,B_),128>>>(pf, in_cf, A, part);
    // 13. reduce + normalize
    cp_reduce_kernel<<<B_,128>>>(part, Apart, cp);
    // 14-17. classifier MLP (M=8 skinny)
    skinny_gemm<true ><<<32,256>>>(cp, c1_w, c1_b, h1, 1024, D_);
    skinny_gemm<true ><<<32,256>>>(h1, c2_w, c2_b, h2, 1024, 1024);
    skinny_gemm<true ><<<8, 256>>>(h2, c3_w, c3_b, h3, 256, 1024);
    skinny_gemm<false><<<1, 256>>>(h3, c4_w, c4_b, (float*)d_out, 1, 256);
}

// round 4
// speedup vs baseline: 1.9841x; 1.0795x over previous
#include <cuda_runtime.h>
#include <math.h>
#include <stdint.h>

#define B_  8
#define LP_ 1000
#define NC_ 64
#define D_  128
#define E_  320
#define NTILE_ 100
#define ITILE_ 10
typedef long long ll;

// ---------------- scratch (device globals) ----------------------------------
__device__ __align__(16) float g_Q  [B_*LP_*D_];
__device__ __align__(16) float g_K  [B_*LP_*D_];
__device__ __align__(16) float g_V  [B_*LP_*D_];
__device__ __align__(16) float g_AV0[B_*LP_*D_];
__device__ __align__(16) float g_AV1[B_*LP_*D_];
__device__ __align__(16) float g_AV [B_*LP_*D_];
__device__ __align__(16) float g_pf [B_*LP_*D_];
__device__ __align__(16) float g_P  [B_*LP_*D_];
__device__ __align__(16) float g_C  [B_*NC_*D_];
__device__ __align__(16) float g_S  [B_*LP_*LP_];
__device__ __align__(16) float g_A  [B_*LP_*NC_];
__device__ __align__(16) float g_Wq [E_*D_];
__device__ __align__(16) float g_bq [D_];
__device__ __align__(16) float g_Apart[B_*16];
__device__ __align__(16) float g_part[B_*NTILE_*D_];
__device__ __align__(16) float g_cp [B_*D_];
__device__ __align__(16) float g_h1 [B_*1024];
__device__ __align__(16) float g_h2 [B_*1024];
__device__ __align__(16) float g_h3 [B_*256];

// ---------------- tf32 helpers ----------------------------------------------
__device__ __forceinline__ uint32_t f2tf32(float x) {
    uint32_t r;
    asm("cvt.rna.tf32.f32 %0, %1;" : "=r"(r) : "f"(x));
    return r;
}
__device__ __forceinline__ void mma_tf32(float* d, const uint32_t* a, const uint32_t* b) {
    asm volatile(
        "mma.sync.aligned.m16n8k8.row.col.f32.tf32.tf32.f32 "
        "{%0,%1,%2,%3}, {%4,%5,%6,%7}, {%8,%9}, {%0,%1,%2,%3};\n"
        : "+f"(d[0]), "+f"(d[1]), "+f"(d[2]), "+f"(d[3])
        : "r"(a[0]), "r"(a[1]), "r"(a[2]), "r"(a[3]), "r"(b[0]), "r"(b[1]));
}
__device__ __forceinline__ void cvt_store4(uint2* base, int idx, float4 v) {
    uint32_t h0 = f2tf32(v.x), h1 = f2tf32(v.y), h2 = f2tf32(v.z), h3 = f2tf32(v.w);
    uint4 p0 = make_uint4(h0, f2tf32(v.x - __uint_as_float(h0)),
                          h1, f2tf32(v.y - __uint_as_float(h1)));
    uint4 p1 = make_uint4(h2, f2tf32(v.z - __uint_as_float(h2)),
                          h3, f2tf32(v.w - __uint_as_float(h3)));
    *(uint4*)(base + idx)     = p0;
    *(uint4*)(base + idx + 2) = p1;
}
__device__ __forceinline__ void cvt_store2(uint2* base, int idx, float2 v) {
    uint32_t h0 = f2tf32(v.x), h1 = f2tf32(v.y);
    *(uint4*)(base + idx) = make_uint4(h0, f2tf32(v.x - __uint_as_float(h0)),
                                       h1, f2tf32(v.y - __uint_as_float(h1)));
}

// ---------------- big GEMM body: 64(M) x 128(N) tile, BK=8 ------------------
// 8 warps = 2M x 4N, warp tile 32x32.  smem: A [m][k] pitch 12 (uint2),
// trans-B [n][k] pitch 12, non-trans-B [k][n] pitch 132. 3xTF32 compensation.
template<bool TRANS_B, bool RELU_A>
__device__ __forceinline__ void gemm_big_body(
    const float* __restrict__ A, const float* __restrict__ Bm,
    const float* __restrict__ bias, float* __restrict__ C,
    int M, int N, int K, float alpha, int m0, int n0,
    uint2* As, uint2* Bs)
{
    constexpr int ASN = 64 * 12;
    constexpr int BSN = TRANS_B ? 128 * 12 : 8 * 132;

    int t = threadIdx.x, warp = t >> 5, lane = t & 31;
    int g = lane >> 2, l3 = lane & 3;
    int wm = (warp & 1) * 32, wn = (warp >> 1) * 32;

    float acc[2][4][4] = {};

    int ar  = t >> 2, ak  = (t & 3) * 2;   // A: row 0..63, k-pair
    int btr = t >> 1, btk = (t & 1) * 4;   // trans-B: row 0..127, k-quad
    int bk  = t >> 5, bnq = (t & 31) * 4;  // non-trans-B: k 0..7, n-quad

    int kt = (K + 7) >> 3;
    float2 ra; float4 rb;

    // prologue
    {
        int gm = m0 + ar, gk = ak;
        ra = make_float2(0.f, 0.f);
        if (gm < M && gk < K) ra = *(const float2*)(A + (ll)gm * K + gk);
        if (RELU_A) { ra.x = fmaxf(ra.x, 0.f); ra.y = fmaxf(ra.y, 0.f); }
        rb = make_float4(0.f, 0.f, 0.f, 0.f);
        if (TRANS_B) {
            int gn = n0 + btr;
            if (gn < N && btk < K) rb = *(const float4*)(Bm + (ll)gn * K + btk);
        } else {
            int gn = n0 + bnq;
            if (bk < K && gn < N) rb = *(const float4*)(Bm + (ll)bk * N + gn);
        }
        cvt_store2(As, ar * 12 + ak, ra);
        if (TRANS_B) cvt_store4(Bs, btr * 12 + btk, rb);
        else         cvt_store4(Bs, bk * 132 + bnq, rb);
    }
    __syncthreads();

    for (int it = 0; it < kt; it++) {
        int s = it & 1;
        if (it + 1 < kt) {
            int k0 = (it + 1) << 3;
            int gm = m0 + ar, gk = k0 + ak;
            ra = make_float2(0.f, 0.f);
            if (gm < M && gk < K) ra = *(const float2*)(A + (ll)gm * K + gk);
            if (RELU_A) { ra.x = fmaxf(ra.x, 0.f); ra.y = fmaxf(ra.y, 0.f); }
            rb = make_float4(0.f, 0.f, 0.f, 0.f);
            if (TRANS_B) {
                int gn = n0 + btr, gk2 = k0 + btk;
                if (gn < N && gk2 < K) rb = *(const float4*)(Bm + (ll)gn * K + gk2);
            } else {
                int gk2 = k0 + bk, gn = n0 + bnq;
                if (gk2 < K && gn < N) rb = *(const float4*)(Bm + (ll)gk2 * N + gn);
            }
        }
        // fragments
        uint32_t ahi[2][4], alo[2][4];
        #pragma unroll
        for (int mi = 0; mi < 2; mi++) {
            int rr = wm + mi * 16 + g;
            uint2 x0 = As[s * ASN + rr * 12 + l3];
            uint2 x1 = As[s * ASN + (rr + 8) * 12 + l3];
            uint2 x2 = As[s * ASN + rr * 12 + l3 + 4];
            uint2 x3 = As[s * ASN + (rr + 8) * 12 + l3 + 4];
            ahi[mi][0] = x0.x; alo[mi][0] = x0.y;
            ahi[mi][1] = x1.x; alo[mi][1] = x1.y;
            ahi[mi][2] = x2.x; alo[mi][2] = x2.y;
            ahi[mi][3] = x3.x; alo[mi][3] = x3.y;
        }
        uint32_t bhi[4][2], blo[4][2];
        #pragma unroll
        for (int ni = 0; ni < 4; ni++) {
            int cc = wn + ni * 8 + g;
            uint2 y0 = TRANS_B ? Bs[s * BSN + cc * 12 + l3]
                               : Bs[s * BSN + l3 * 132 + cc];
            uint2 y1 = TRANS_B ? Bs[s * BSN + cc * 12 + l3 + 4]
                               : Bs[s * BSN + (l3 + 4) * 132 + cc];
            bhi[ni][0] = y0.x; blo[ni][0] = y0.y;
            bhi[ni][1] = y1.x; blo[ni][1] = y1.y;
        }
        #pragma unroll
        for (int mi = 0; mi < 2; mi++)
            #pragma unroll
            for (int ni = 0; ni < 4; ni++) {
                mma_tf32(acc[mi][ni], ahi[mi], bhi[ni]);
                mma_tf32(acc[mi][ni], ahi[mi], blo[ni]);
                mma_tf32(acc[mi][ni], alo[mi], bhi[ni]);
            }
        if (it + 1 < kt) {
            int so = s ^ 1;
            cvt_store2(As + so * ASN, ar * 12 + ak, ra);
            if (TRANS_B) cvt_store4(Bs + so * BSN, btr * 12 + btk, rb);
            else         cvt_store4(Bs + so * BSN, bk * 132 + bnq, rb);
        }
        __syncthreads();
    }

    // epilogue
    #pragma unroll
    for (int mi = 0; mi < 2; mi++)
        #pragma unroll
        for (int ni = 0; ni < 4; ni++) {
            int r0 = m0 + wm + mi * 16 + g;
            int c0 = n0 + wn + ni * 8 + 2 * l3;
            if (c0 >= N) continue;
            float b0 = 0.f, b1 = 0.f;
            if (bias) { b0 = bias[c0]; b1 = bias[c0 + 1]; }
            if (r0 < M) {
                float2 v = make_float2(acc[mi][ni][0] * alpha + b0,
                                       acc[mi][ni][1] * alpha + b1);
                *(float2*)(C + (ll)r0 * N + c0) = v;
            }
            if (r0 + 8 < M) {
                float2 v = make_float2(acc[mi][ni][2] * alpha + b0,
                                       acc[mi][ni][3] * alpha + b1);
                *(float2*)(C + (ll)(r0 + 8) * N + c0) = v;
            }
        }
}

// ---------------- big GEMM wrappers ------------------------------------------
template<bool TRANS_B, bool RELU_A>
__global__ void __launch_bounds__(256, 2)
gemm_big_std(const float* __restrict__ A, const float* __restrict__ Bm,
             const float* __restrict__ bias, float* __restrict__ C,
             int M, int N, int K, ll sA, ll sB, ll sC, float alpha)
{
    __shared__ __align__(16) uint2 As[2 * 64 * 12];
    __shared__ __align__(16) uint2 Bs[2 * (TRANS_B ? 128 * 12 : 8 * 132)];
    int bz = blockIdx.z;
    gemm_big_body<TRANS_B, RELU_A>(A + bz * sA, Bm + bz * sB, bias, C + bz * sC,
        M, N, K, alpha, blockIdx.y * 64, blockIdx.x * 128, As, Bs);
}

__global__ void __launch_bounds__(256, 2)
gemm_qkv(const float* __restrict__ in_pe, const float* __restrict__ Wq,
         const float* __restrict__ bq, float* __restrict__ Q,
         const float* __restrict__ in_pfx,
         const float* __restrict__ wk_w, const float* __restrict__ wk_b,
         float* __restrict__ Kb,
         const float* __restrict__ wv_w, const float* __restrict__ wv_b,
         float* __restrict__ Vb)
{
    __shared__ __align__(16) uint2 As[2 * 64 * 12];
    __shared__ __align__(16) uint2 Bs[2 * 8 * 132];
    int m0 = blockIdx.y * 64;
    if (blockIdx.z == 0)
        gemm_big_body<false, false>(in_pe, Wq, bq, Q, B_*LP_, D_, E_, 1.f, m0, 0, As, Bs);
    else if (blockIdx.z == 1)
        gemm_big_body<false, false>(in_pfx, wk_w, wk_b, Kb, B_*LP_, D_, D_, 1.f, m0, 0, As, Bs);
    else
        gemm_big_body<false, false>(in_pfx, wv_w, wv_b, Vb, B_*LP_, D_, D_, 1.f, m0, 0, As, Bs);
}

__global__ void __launch_bounds__(256, 2)
gemm_pc(const float* __restrict__ pf, const float* __restrict__ jp_w,
        const float* __restrict__ jp_b, float* __restrict__ P,
        const float* __restrict__ cf, const float* __restrict__ jc_w,
        const float* __restrict__ jc_b, float* __restrict__ C)
{
    if (blockIdx.z == 1 && blockIdx.y >= 8) return;
    __shared__ __align__(16) uint2 As[2 * 64 * 12];
    __shared__ __align__(16) uint2 Bs[2 * 8 * 132];
    int m0 = blockIdx.y * 64;
    if (blockIdx.z == 0)
        gemm_big_body<false, true>(pf, jp_w, jp_b, P, B_*LP_, D_, D_, 1.f, m0, 0, As, Bs);
    else
        gemm_big_body<false, true>(cf, jc_w, jc_b, C, B_*NC_, D_, D_, 1.f, m0, 0, As, Bs);
}

// AV split-K: z = batch*2 + half
__global__ void __launch_bounds__(256, 2)
gemm_av(const float* __restrict__ S, const float* __restrict__ V,
        float* __restrict__ AV0, float* __restrict__ AV1)
{
    __shared__ __align__(16) uint2 As[2 * 64 * 12];
    __shared__ __align__(16) uint2 Bs[2 * 8 * 132];
    int b = blockIdx.z >> 1, half = blockIdx.z & 1;
    int kOff = half * 512, kLen = half ? 488 : 512;
    float* out = half ? AV1 : AV0;
    gemm_big_body<false, false>(
        S + (ll)b * LP_ * LP_ + kOff,
        V + ((ll)b * LP_ + kOff) * D_,
        nullptr, out + (ll)b * LP_ * D_,
        LP_, D_, kLen, 1.f, blockIdx.y * 64, 0, As, Bs);
}

__global__ void add_av(const float* __restrict__ a, const float* __restrict__ b,
                       float* __restrict__ c)
{
    int i = (blockIdx.x * 256 + threadIdx.x) * 4;
    float4 x = *(const float4*)(a + i), y = *(const float4*)(b + i);
    x.x += y.x; x.y += y.y; x.z += y.z; x.w += y.w;
    *(float4*)(c + i) = x;
}

// ---------------- A-logits: 64x64 tile GEMM + sigmoid + partial sums --------
// grid (16 m-tiles, 8 batches), A = P [1000x128], B = C [64x128] (trans), N=64.
__global__ void __launch_bounds__(256, 2)
alogits_kernel(const float* __restrict__ Pm, const float* __restrict__ Cm,
               float* __restrict__ Aout, float* __restrict__ Apart)
{
    __shared__ __align__(16) uint2 As[2][64 * 20];
    __shared__ __align__(16) uint2 Bs[2][64 * 20];
    __shared__ float red[256];

    int b = blockIdx.y, mt = blockIdx.x;
    const float* A = Pm + (ll)b * LP_ * D_;
    const float* Bm = Cm + (ll)b * NC_ * D_;
    float* C = Aout + (ll)b * LP_ * NC_;
    int m0 = mt * 64;
    int t = threadIdx.x, warp = t >> 5, lane = t & 31;
    int g = lane >> 2, l3 = lane & 3;
    int wm = (warp & 1) * 32, wn = (warp >> 1) * 16;

    float acc[2][2][4] = {};
    int arow = t >> 2, akq = (t & 3) * 4;
    const int K = D_, M = LP_;
    int kt = K >> 4;  // 8
    float4 ra, rb;
    {
        int gm = m0 + arow;
        ra = make_float4(0.f, 0.f, 0.f, 0.f);
        if (gm < M) ra = *(const float4*)(A + (ll)gm * K + akq);
        rb = *(const float4*)(Bm + (ll)arow * K + akq);
        cvt_store4(As[0], arow * 20 + akq, ra);
        cvt_store4(Bs[0], arow * 20 + akq, rb);
    }
    __syncthreads();
    for (int it = 0; it < kt; it++) {
        int s = it & 1;
        if (it + 1 < kt) {
            int k0 = (it + 1) << 4;
            int gm = m0 + arow;
            ra = make_float4(0.f, 0.f, 0.f, 0.f);
            if (gm < M) ra = *(const float4*)(A + (ll)gm * K + k0 + akq);
            rb = *(const float4*)(Bm + (ll)arow * K + k0 + akq);
        }
        #pragma unroll
        for (int ks = 0; ks < 2; ks++) {
            int kb = ks * 8 + l3;
            uint32_t ahi[2][4], alo[2][4];
            #pragma unroll
            for (int mi = 0; mi < 2; mi++) {
                int rr = wm + mi * 16 + g;
                uint2 x0 = As[s][rr * 20 + kb];
                uint2 x1 = As[s][(rr + 8) * 20 + kb];
                uint2 x2 = As[s][rr * 20 + kb + 4];
                uint2 x3 = As[s][(rr + 8) * 20 + kb + 4];
                ahi[mi][0] = x0.x; alo[mi][0] = x0.y;
                ahi[mi][1] = x1.x; alo[mi][1] = x1.y;
                ahi[mi][2] = x2.x; alo[mi][2] = x2.y;
                ahi[mi][3] = x3.x; alo[mi][3] = x3.y;
            }
            uint32_t bhi[2][2], blo[2][2];
            #pragma unroll
            for (int ni = 0; ni < 2; ni++) {
                int cc = wn + ni * 8 + g;
                uint2 y0 = Bs[s][cc * 20 + kb];
                uint2 y1 = Bs[s][cc * 20 + kb + 4];
                bhi[ni][0] = y0.x; blo[ni][0] = y0.y;
                bhi[ni][1] = y1.x; blo[ni][1] = y1.y;
            }
            #pragma unroll
            for (int mi = 0; mi < 2; mi++)
                #pragma unroll
                for (int ni = 0; ni < 2; ni++) {
                    mma_tf32(acc[mi][ni], ahi[mi], bhi[ni]);
                    mma_tf32(acc[mi][ni], ahi[mi], blo[ni]);
                    mma_tf32(acc[mi][ni], alo[mi], bhi[ni]);
                }
        }
        if (it + 1 < kt) {
            cvt_store4(As[s ^ 1], arow * 20 + akq, ra);
            cvt_store4(Bs[s ^ 1], arow * 20 + akq, rb);
        }
        __syncthreads();
    }

    // sigmoid epilogue + partial sum
    float tsum = 0.f;
    #pragma unroll
    for (int mi = 0; mi < 2; mi++)
        #pragma unroll
        for (int ni = 0; ni < 2; ni++) {
            int r0 = m0 + wm + mi * 16 + g;
            int c0 = wn + ni * 8 + 2 * l3;
            if (r0 < M) {
                float v0 = 1.f / (1.f + __expf(-acc[mi][ni][0]));
                float v1 = 1.f / (1.f + __expf(-acc[mi][ni][1]));
                *(float2*)(C + (ll)r0 * NC_ + c0) = make_float2(v0, v1);
                tsum += v0 + v1;
            }
            if (r0 + 8 < M) {
                float v0 = 1.f / (1.f + __expf(-acc[mi][ni][2]));
                float v1 = 1.f / (1.f + __expf(-acc[mi][ni][3]));
                *(float2*)(C + (ll)(r0 + 8) * NC_ + c0) = make_float2(v0, v1);
                tsum += v0 + v1;
            }
        }
    red[t] = tsum; __syncthreads();
    for (int s2 = 128; s2 > 0; s2 >>= 1) {
        if (t < s2) red[t] += red[t + s2];
        __syncthreads();
    }
    if (t == 0) Apart[b * 16 + mt] = red[0];
}

// ---------------- bq' = emb_b @ wq_w + wq_b ---------------------------------
__global__ void fuse_bq_kernel(const float* __restrict__ emb_b,
                               const float* __restrict__ wq_w,
                               const float* __restrict__ wq_b,
                               float* __restrict__ bq)
{
    int n = threadIdx.x;
    float s = wq_b[n];
    for (int k = 0; k < D_; k++) s = fmaf(emb_b[k], wq_w[k * D_ + n], s);
    bq[n] = s;
}

// ---------------- row softmax -------------------------------------------------
__global__ void softmax_kernel(float* __restrict__ S)
{
    ll row = blockIdx.x;
    float* p = S + row * LP_;
    int t = threadIdx.x;  // 256
    __shared__ float red[256];
    float v[4];
    float mx = -1e30f;
    #pragma unroll
    for (int e = 0; e < 4; e++) {
        int i = t + e * 256;
        v[e] = (i < LP_) ? p[i] : -1e30f;
        mx = fmaxf(mx, v[e]);
    }
    red[t] = mx; __syncthreads();
    for (int s = 128; s > 0; s >>= 1) {
        if (t < s) red[t] = fmaxf(red[t], red[t + s]);
        __syncthreads();
    }
    mx = red[0];
    __syncthreads();
    float sum = 0.f;
    #pragma unroll
    for (int e = 0; e < 4; e++) { v[e] = __expf(v[e] - mx); sum += v[e]; }
    red[t] = sum; __syncthreads();
    for (int s = 128; s > 0; s >>= 1) {
        if (t < s) red[t] += red[t + s];
        __syncthreads();
    }
    float inv = 1.f / red[0];
    #pragma unroll
    for (int e = 0; e < 4; e++) {
        int i = t + e * 256;
        if (i < LP_) p[i] = v[e] * inv;
    }
}

// ---------------- tanh outer-product weighted reduction ---------------------
__global__ void tanh_outer_kernel(const float* __restrict__ pf,
                                  const float* __restrict__ cf,
                                  const float* __restrict__ A,
                                  float* __restrict__ part)
{
    int b = blockIdx.y, tile = blockIdx.x;
    int d = threadIdx.x;  // 128
    __shared__ float cfs[NC_ * D_];
    for (int i = threadIdx.x; i < NC_ * D_; i += 128)
        cfs[i] = cf[(ll)b * NC_ * D_ + i];
    __syncthreads();
    float acc = 0.f;
    int i0 = tile * ITILE_;
    for (int i = i0; i < i0 + ITILE_; i++) {
        float pv = pf[((ll)b * LP_ + i) * D_ + d];
        const float* Ar = A + ((ll)b * LP_ + i) * NC_;
        #pragma unroll 4
        for (int k = 0; k < NC_; k++) {
            float w = Ar[k];
            float x = pv * cfs[k * D_ + d];
            float th;
            asm("tanh.approx.f32 %0, %1;" : "=f"(th) : "f"(x));
            acc = fmaf(th, w, acc);
        }
    }
    part[((ll)b * NTILE_ + tile) * D_ + d] = acc;
}

__global__ void cp_reduce_kernel(const float* __restrict__ part,
                                 const float* __restrict__ Apart,
                                 float* __restrict__ cp)
{
    int b = blockIdx.x;
    int d = threadIdx.x;  // 128
    float as = 0.f;
    #pragma unroll
    for (int j = 0; j < 16; j++) as += Apart[b * 16 + j];
    float s = 0.f;
    for (int t2 = 0; t2 < NTILE_; t2++)
        s += part[((ll)b * NTILE_ + t2) * D_ + d];
    cp[b * D_ + d] = s / as;
}

// ---------------- skinny GEMM (M = 8 rows) -----------------------------------
template<bool RELU_OUT>
__global__ void __launch_bounds__(256)
skinny_gemm(const float* __restrict__ A, const float* __restrict__ W,
            const float* __restrict__ bias, float* __restrict__ C,
            int N, int K)
{
    __shared__ float As[8 * 1024];
    __shared__ float red[8][8][32];
    int t = threadIdx.x;
    for (int i = t; i < 8 * K; i += 256) As[i] = A[i];
    __syncthreads();
    int n = blockIdx.x * 32 + (t & 31);
    int ks = t >> 5;
    int kseg = K >> 3;
    float acc[8] = {};
    if (n < N) {
        for (int k = ks * kseg; k < (ks + 1) * kseg; k++) {
            float w = W[(ll)k * N + n];
            #pragma unroll
            for (int m = 0; m < 8; m++) acc[m] = fmaf(As[m * K + k], w, acc[m]);
        }
    }
    #pragma unroll
    for (int m = 0; m < 8; m++) red[ks][m][t & 31] = acc[m];
    __syncthreads();
    int m = t >> 5, lnn = t & 31;
    int nn = blockIdx.x * 32 + lnn;
    if (nn < N) {
        float s = 0.f;
        #pragma unroll
        for (int j = 0; j < 8; j++) s += red[j][m][lnn];
        s += bias[nn];
        if (RELU_OUT) s = fmaxf(s, 0.f);
        C[(ll)m * N + nn] = s;
    }
}

// ---------------- launch ------------------------------------------------------
extern "C" void kernel_launch(void* const* d_in, const int* in_sizes, int n_in,
                              void* d_out, int out_size)
{
    const float* in_pe  = (const float*)d_in[0];
    const float* in_pfx = (const float*)d_in[1];
    const float* in_cf  = (const float*)d_in[2];
    const float* emb_w = (const float*)d_in[3];  const float* emb_b = (const float*)d_in[4];
    const float* wq_w  = (const float*)d_in[5];  const float* wq_b  = (const float*)d_in[6];
    const float* wk_w  = (const float*)d_in[7];  const float* wk_b  = (const float*)d_in[8];
    const float* wv_w  = (const float*)d_in[9];  const float* wv_b  = (const float*)d_in[10];
    const float* wo_w  = (const float*)d_in[11]; const float* wo_b  = (const float*)d_in[12];
    const float* jp_w  = (const float*)d_in[13]; const float* jp_b  = (const float*)d_in[14];
    const float* jc_w  = (const float*)d_in[15]; const float* jc_b  = (const float*)d_in[16];
    const float* c1_w  = (const float*)d_in[17]; const float* c1_b  = (const float*)d_in[18];
    const float* c2_w  = (const float*)d_in[19]; const float* c2_b  = (const float*)d_in[20];
    const float* c3_w  = (const float*)d_in[21]; const float* c3_b  = (const float*)d_in[22];
    const float* c4_w  = (const float*)d_in[23]; const float* c4_b  = (const float*)d_in[24];

    float *Q, *K, *V, *AV0, *AV1, *AV, *pf, *P, *C, *S, *A, *Wq, *bq, *Apart,
          *part, *cp, *h1, *h2, *h3;
    cudaGetSymbolAddress((void**)&Q,    g_Q);
    cudaGetSymbolAddress((void**)&K,    g_K);
    cudaGetSymbolAddress((void**)&V,    g_V);
    cudaGetSymbolAddress((void**)&AV0,  g_AV0);
    cudaGetSymbolAddress((void**)&AV1,  g_AV1);
    cudaGetSymbolAddress((void**)&AV,   g_AV);
    cudaGetSymbolAddress((void**)&pf,   g_pf);
    cudaGetSymbolAddress((void**)&P,    g_P);
    cudaGetSymbolAddress((void**)&C,    g_C);
    cudaGetSymbolAddress((void**)&S,    g_S);
    cudaGetSymbolAddress((void**)&A,    g_A);
    cudaGetSymbolAddress((void**)&Wq,   g_Wq);
    cudaGetSymbolAddress((void**)&bq,   g_bq);
    cudaGetSymbolAddress((void**)&Apart,g_Apart);
    cudaGetSymbolAddress((void**)&part, g_part);
    cudaGetSymbolAddress((void**)&cp,   g_cp);
    cudaGetSymbolAddress((void**)&h1,   g_h1);
    cudaGetSymbolAddress((void**)&h2,   g_h2);
    cudaGetSymbolAddress((void**)&h3,   g_h3);

    const float inv_sqrt_d = 0.088388347648318440550f;  // 1/sqrt(128)

    // 0a. Wq' = emb_w @ wq_w  [320x128]
    gemm_big_std<false,false><<<dim3(1,5,1),256>>>(emb_w, wq_w, nullptr, Wq,
        E_, D_, D_, 0, 0, 0, 1.f);
    // 0b. bq' = emb_b @ wq_w + wq_b
    fuse_bq_kernel<<<1,128>>>(emb_b, wq_w, wq_b, bq);
    // 1. Q/K/V merged
    gemm_qkv<<<dim3(1,125,3),256>>>(in_pe, Wq, bq, Q,
                                    in_pfx, wk_w, wk_b, K, wv_w, wv_b, V);
    // 2. S = Q @ K^T / sqrt(D)
    gemm_big_std<true,false><<<dim3(8,16,B_),256>>>(Q, K, nullptr, S,
        LP_, LP_, D_, (ll)LP_*D_, (ll)LP_*D_, (ll)LP_*LP_, inv_sqrt_d);
    // 3. softmax
    softmax_kernel<<<B_*LP_,256>>>(S);
    // 4. AV = S @ V  (split-K=2)
    gemm_av<<<dim3(1,16,B_*2),256>>>(S, V, AV0, AV1);
    add_av<<<1000,256>>>(AV0, AV1, AV);
    // 5. pf = AV @ wo + b
    gemm_big_std<false,false><<<dim3(1,125,1),256>>>(AV, wo_w, wo_b, pf,
        B_*LP_, D_, D_, 0, 0, 0, 1.f);
    // 6. P = relu(pf)@jp + b ; C = relu(cf)@jc + b (merged)
    gemm_pc<<<dim3(1,125,2),256>>>(pf, jp_w, jp_b, P, in_cf, jc_w, jc_b, C);
    // 7. A = sigmoid(P @ C^T) + partial sums (fused)
    alogits_kernel<<<dim3(16,B_),256>>>(P, C, A, Apart);
    // 8. tanh outer product partials
    tanh_outer_kernel<<<dim3(NTILE_,B_),128>>>(pf, in_cf, A, part);
    // 9. reduce + normalize
    cp_reduce_kernel<<<B_,128>>>(part, Apart, cp);
    // 10-13. classifier MLP
    skinny_gemm<true ><<<32,256>>>(cp, c1_w, c1_b, h1, 1024, D_);
    skinny_gemm<true ><<<32,256>>>(h1, c2_w, c2_b, h2, 1024, 1024);
    skinny_gemm<true ><<<8, 256>>>(h2, c3_w, c3_b, h3, 256, 1024);
    skinny_gemm<false><<<1, 256>>>(h3, c4_w, c4_b, (float*)d_out, 1, 256);
}